// round 14
// baseline (speedup 1.0000x reference)
#include <cuda_runtime.h>
#include <cuda_fp16.h>
#include <cstdint>

// ---------------------------------------------------------------------------
// x:(2048,64,512) fp32, Wq/Wk/Wv/Wo:(512,512) fp32
// out = SDPA(x@WqT, x@WkT, x@WvT) @ WoT    H=16, dk=32, S=64
//
// R14 vs R13: GEMMs go 3-stage->2-stage (smem 96->64KB) with
// __launch_bounds__(128,3) -> 3 CTAs/SM. R12's profile showed tensor pipe
// only 53% busy at 2 warps/SMSP (HMMA rt ~6cyc, warps stalled ~half the
// time) -> a third resident warp per SMSP covers the stalls.
// Preps merged into one launch. All numerics bit-identical to R13.
// ---------------------------------------------------------------------------

#define D_MODEL   512
#define M_ROWS    131072
#define NUM_HEADS 16
#define SEQ       64
#define DK        32

#define MS        ((size_t)M_ROWS * D_MODEL)
#define WELEMS    ((size_t)D_MODEL * D_MODEL)

__device__ __half g_xh[MS];            // x, fp16, pair-permuted along k
__device__ __half g_wh[4 * WELEMS];    // Wq,Wk,Wv,Wo fp16, pair-permuted
__device__ __half g_qkvh[3 * MS];      // q, k, v : head-major [b,h,s,dk]
__device__ __half g_ath[MS];           // attn out: head-major, pair-permuted

// ======================== helpers ==========================================
__device__ __forceinline__ uint32_t smem_u32(const void* p) {
    uint32_t a;
    asm("{ .reg .u64 t; cvta.to.shared.u64 t, %1; cvt.u32.u64 %0, t; }"
        : "=r"(a) : "l"(p));
    return a;
}

#define MMA_F16(d, a0, a1, a2, a3, b0, b1)                                     \
    asm volatile(                                                              \
        "mma.sync.aligned.m16n8k16.row.col.f32.f16.f16.f32 "                   \
        "{%0,%1,%2,%3}, {%4,%5,%6,%7}, {%8,%9}, {%0,%1,%2,%3};"                \
        : "+f"(d[0]), "+f"(d[1]), "+f"(d[2]), "+f"(d[3])                       \
        : "r"(a0), "r"(a1), "r"(a2), "r"(a3), "r"(b0), "r"(b1))

#define LDSM4(r0, r1, r2, r3, a)                                               \
    asm volatile("ldmatrix.sync.aligned.m8n8.x4.shared.b16 "                   \
                 "{%0,%1,%2,%3}, [%4];"                                        \
                 : "=r"(r0), "=r"(r1), "=r"(r2), "=r"(r3) : "r"(a))
#define LDSM4T(r0, r1, r2, r3, a)                                              \
    asm volatile("ldmatrix.sync.aligned.m8n8.x4.trans.shared.b16 "             \
                 "{%0,%1,%2,%3}, [%4];"                                        \
                 : "=r"(r0), "=r"(r1), "=r"(r2), "=r"(r3) : "r"(a))

#define CPA16(sa, gp)                                                          \
    asm volatile("cp.async.cg.shared.global [%0], [%1], 16;"                   \
                 :: "r"(sa), "l"(gp) : "memory")
#define CPA_COMMIT() asm volatile("cp.async.commit_group;" ::: "memory")
#define CPA_WAIT0()  asm volatile("cp.async.wait_group 0;" ::: "memory")
#define LDS64(v, a)                                                            \
    asm volatile("ld.shared.v2.u32 {%0,%1}, [%2];"                             \
                 : "=r"((v).x), "=r"((v).y) : "r"(a))

__device__ __forceinline__ uint32_t packh2(float a, float b) {
    __half2 h = __floats2half2_rn(a, b);
    return *(uint32_t*)&h;
}

// Head-major address for logical (row=(b,s), col=(h,dk)) in halves.
__device__ __forceinline__ size_t hm_idx(int row, int col) {
    return ((size_t)(row >> 6) << 15) + ((size_t)(col >> 5) << 11) +
           ((size_t)(row & 63) << 5) + (size_t)(col & 31);
}

// ======================== prep (x + all W in one launch) ===================
__device__ __forceinline__ void prep16(const float* f, uint32_t* o) {
#pragma unroll
    for (int j = 0; j < 8; j++)
        o[((j & 3) << 1) + (j >> 2)] = packh2(f[2 * j], f[2 * j + 1]);
}

#define PREPX_BLOCKS 16384

__global__ void __launch_bounds__(256)
prep_all(const float* __restrict__ x,
         const float* __restrict__ w0, const float* __restrict__ w1,
         const float* __restrict__ w2, const float* __restrict__ w3,
         __half* __restrict__ xh, __half* __restrict__ wh) {
    const int bid = blockIdx.x;
    const float* src;
    __half* dst;
    size_t g;
    if (bid < PREPX_BLOCKS) {
        g   = (size_t)bid * 256 + threadIdx.x;   // group of 16 in x
        src = x + g * 16;
        dst = xh;
    } else {
        size_t gw = (size_t)(bid - PREPX_BLOCKS) * 256 + threadIdx.x;
        int wsel = (int)(gw >> 14);               // 16384 groups per W
        const float* w = wsel == 0 ? w0 : wsel == 1 ? w1 : wsel == 2 ? w2 : w3;
        src = w + (gw & 16383) * 16;
        dst = wh;
        g   = gw;
    }
    float f[16];
#pragma unroll
    for (int q = 0; q < 4; q++)
        *(float4*)&f[4 * q] = ((const float4*)src)[q];
    uint32_t o[8];
    prep16(f, o);
    ((uint4*)dst)[2 * g]     = make_uint4(o[0], o[1], o[2], o[3]);
    ((uint4*)dst)[2 * g + 1] = make_uint4(o[4], o[5], o[6], o[7]);
}

// ======================== GEMM common pieces ===============================
// Block 128x128, BK=64 halves (128B/row), 128 threads = 4 warps (2Mx2N),
// warp tile 64x64. Stage = A(16KB)+B(16KB); 2 stages = 64KB; 3 CTAs/SM.
#define GSTAGE  32768
#define GSMEM   (2 * GSTAGE + 128)

#define GEMM_COMPUTE(sbase, s)                                                 \
    do {                                                                       \
        const uint32_t sA =                                                    \
            (sbase) + (s)*GSTAGE + (wm * 64 + r8) * 128 + 8 * (c & 1);         \
        const uint32_t sB = (sbase) + (s)*GSTAGE + 16384 + wn * 8192 +         \
                            r8 * 128 + 8 * (c & 1);                            \
        _Pragma("unroll") for (int g = 0; g < 4; g++) {                        \
            const uint32_t csw = (uint32_t)(((2 * g + (c >> 1)) ^ r8) << 4);   \
            uint2 lo, hi;                                                      \
            unsigned a0[4], a1[4], a2[4], a3[4], b0[8], b1[8];                 \
            _Pragma("unroll") for (int mt = 0; mt < 4; mt++) {                 \
                LDS64(lo, sA + mt * 2048 + csw);                               \
                LDS64(hi, sA + mt * 2048 + 1024 + csw);                        \
                a0[mt] = lo.x; a2[mt] = lo.y; a1[mt] = hi.x; a3[mt] = hi.y;    \
            }                                                                  \
            _Pragma("unroll") for (int nt = 0; nt < 8; nt++) {                 \
                LDS64(lo, sB + nt * 1024 + csw);                               \
                b0[nt] = lo.x; b1[nt] = lo.y;                                  \
            }                                                                  \
            _Pragma("unroll") for (int mt = 0; mt < 4; mt++)                   \
                _Pragma("unroll") for (int nt = 0; nt < 8; nt++)               \
                    MMA_F16(acc[mt][nt], a0[mt], a1[mt], a2[mt], a3[mt],       \
                            b0[nt], b1[nt]);                                   \
        }                                                                      \
    } while (0)

// ======================== GEMM: QKV (fp16 A -> head-major fp16 C) ==========
__global__ void __launch_bounds__(128, 3)
gemm_qkv(const __half* __restrict__ A, const __half* __restrict__ Wt,
         __half* __restrict__ C, size_t c_stride) {
    extern __shared__ char dsmem[];
    const uint32_t sb = (smem_u32(dsmem) + 127u) & ~127u;

    const int tid  = threadIdx.x;
    const int lane = tid & 31;
    const int wid  = tid >> 5;
    const int wm   = wid & 1;
    const int wn   = wid >> 1;
    const int c    = lane & 3;
    const int r8   = lane >> 2;

    const int nb   = blockIdx.x;
    const int wsel = nb >> 2;
    const int n0   = (nb & 3) * 128;
    const int m0   = blockIdx.y * 128;

    const __half* Aw = A + (size_t)m0 * 512;
    const __half* Bw = Wt + (size_t)wsel * WELEMS + (size_t)n0 * 512;

    float acc[4][8][4];
#pragma unroll
    for (int mt = 0; mt < 4; mt++)
#pragma unroll
        for (int nt = 0; nt < 8; nt++)
#pragma unroll
            for (int i = 0; i < 4; i++) acc[mt][nt][i] = 0.0f;

    auto load_stage = [&](int s, int kt) {
        const uint32_t stage = sb + s * GSTAGE;
#pragma unroll
        for (int i = 0; i < 16; i++) {
            const int cid = tid + i * 128;
            const int isB = cid >> 10;
            const int r   = (cid >> 3) & 127;
            const int ch  = cid & 7;
            const uint32_t so =
                stage + isB * 16384 + r * 128 + (((ch ^ (r & 7)) << 4));
            const __half* gp =
                (isB ? Bw : Aw) + (size_t)r * 512 + kt * 64 + ch * 8;
            CPA16(so, gp);
        }
        CPA_COMMIT();
    };

    load_stage(0, 0);
    int scur = 0;
#pragma unroll 1
    for (int kt = 0; kt < 8; kt++) {
        CPA_WAIT0();
        __syncthreads();
        if (kt + 1 < 8) load_stage(scur ^ 1, kt + 1);
        GEMM_COMPUTE(sb, scur);
        scur ^= 1;
    }

    __half* Ch = C + (size_t)wsel * c_stride;
#pragma unroll
    for (int mt = 0; mt < 4; mt++) {
        const int row = m0 + wm * 64 + mt * 16 + r8;
#pragma unroll
        for (int nt = 0; nt < 8; nt++) {
            const int off = n0 + wn * 64 + nt * 8 + 2 * c;
            const size_t a = hm_idx(row, off);
            *(__half2*)&Ch[a] =
                __floats2half2_rn(acc[mt][nt][0], acc[mt][nt][1]);
            *(__half2*)&Ch[a + 256] =   // s+8 -> +8*32 halves
                __floats2half2_rn(acc[mt][nt][2], acc[mt][nt][3]);
        }
    }
}

// ======================== GEMM: Wo (head-major gather A -> fp32 C) =========
__global__ void __launch_bounds__(128, 3)
gemm_wo(const __half* __restrict__ A, const __half* __restrict__ Wt,
        float* __restrict__ C) {
    extern __shared__ char dsmem[];
    const uint32_t sb = (smem_u32(dsmem) + 127u) & ~127u;

    const int tid  = threadIdx.x;
    const int lane = tid & 31;
    const int wid  = tid >> 5;
    const int wm   = wid & 1;
    const int wn   = wid >> 1;
    const int c    = lane & 3;
    const int r8   = lane >> 2;

    const int n0 = blockIdx.x * 128;
    const int m0 = blockIdx.y * 128;

    const __half* Bw = Wt + (size_t)n0 * 512;

    float acc[4][8][4];
#pragma unroll
    for (int mt = 0; mt < 4; mt++)
#pragma unroll
        for (int nt = 0; nt < 8; nt++)
#pragma unroll
            for (int i = 0; i < 4; i++) acc[mt][nt][i] = 0.0f;

    auto load_stage = [&](int s, int kt) {
        const uint32_t stage = sb + s * GSTAGE;
#pragma unroll
        for (int i = 0; i < 16; i++) {
            const int cid = tid + i * 128;
            const int isB = cid >> 10;
            const int r   = (cid >> 3) & 127;
            const int ch  = cid & 7;
            const uint32_t so =
                stage + isB * 16384 + r * 128 + (((ch ^ (r & 7)) << 4));
            const __half* gp =
                isB ? (Bw + (size_t)r * 512 + kt * 64 + ch * 8)
                    : (A + hm_idx(m0 + r, kt * 64 + ch * 8));
            CPA16(so, gp);
        }
        CPA_COMMIT();
    };

    load_stage(0, 0);
    int scur = 0;
#pragma unroll 1
    for (int kt = 0; kt < 8; kt++) {
        CPA_WAIT0();
        __syncthreads();
        if (kt + 1 < 8) load_stage(scur ^ 1, kt + 1);
        GEMM_COMPUTE(sb, scur);
        scur ^= 1;
    }

#pragma unroll
    for (int mt = 0; mt < 4; mt++) {
        const int row = m0 + wm * 64 + mt * 16 + r8;
#pragma unroll
        for (int nt = 0; nt < 8; nt++) {
            const int col = n0 + wn * 64 + nt * 8 + 2 * c;
            *(float2*)&C[(size_t)row * 512 + col] =
                make_float2(acc[mt][nt][0], acc[mt][nt][1]);
            *(float2*)&C[(size_t)(row + 8) * 512 + col] =
                make_float2(acc[mt][nt][2], acc[mt][nt][3]);
        }
    }
}

// ======================== attention (fp16 mma.sync + ldmatrix) =============
// One block (128 threads) per (batch, head). q,k,v head-major: each tensor
// slab for this block is 4KB CONTIGUOUS -> fully coalesced staging.
// Row stride 40 halves (80B) keeps every ldmatrix phase conflict-free.
// P stays in registers (S-fragment == PV A-fragment).
__global__ void __launch_bounds__(128, 8)
attn64_f16(const __half* __restrict__ Q, const __half* __restrict__ K,
           const __half* __restrict__ V, __half* __restrict__ At) {
    __shared__ __half Qs[64][40];
    __shared__ __half Ks[64][40];
    __shared__ __half Vs[64][40];

    const int tid  = threadIdx.x;
    const int lane = tid & 31;
    const int w    = tid >> 5;
    const int c    = lane & 3;
    const int r8   = lane >> 2;

    const int bh = blockIdx.x;                 // b*16 + h
    const size_t base = (size_t)bh * 2048;     // [b,h] slab, 64x32 halves

    {
        const uint4* qg = (const uint4*)(Q + base);
        const uint4* kg = (const uint4*)(K + base);
        const uint4* vg = (const uint4*)(V + base);
#pragma unroll
        for (int i = 0; i < 2; i++) {
            const int ci  = tid + i * 128;
            const int row = ci >> 2, p = ci & 3;
            *(uint4*)&Qs[row][p * 8] = qg[ci];
            *(uint4*)&Ks[row][p * 8] = kg[ci];
            *(uint4*)&Vs[row][p * 8] = vg[ci];
        }
    }
    __syncthreads();

    const int l7  = lane & 7;
    const int t01 = (lane >> 3) & 1;
    const int t23 = lane >> 4;

    // ---- S = Q K^T  (M=16/warp, N=64, K=32 -> 2 k16 groups) ----
    const uint32_t aQ = smem_u32(&Qs[0][0]) +
                        (w * 16 + t01 * 8 + l7) * 80 + t23 * 16;
    const uint32_t bK = smem_u32(&Ks[0][0]) +
                        (t23 * 8 + l7) * 80 + t01 * 16;
    float s[8][4];
#pragma unroll
    for (int nt = 0; nt < 8; nt++)
#pragma unroll
        for (int i = 0; i < 4; i++) s[nt][i] = 0.0f;

#pragma unroll
    for (int g = 0; g < 2; g++) {
        uint32_t a0, a1, a2, a3;
        LDSM4(a0, a1, a2, a3, aQ + g * 32);
#pragma unroll
        for (int np = 0; np < 4; np++) {
            uint32_t b0, b1, b2, b3;
            LDSM4(b0, b1, b2, b3, bK + np * (16 * 80) + g * 32);
            MMA_F16(s[2 * np],     a0, a1, a2, a3, b0, b1);
            MMA_F16(s[2 * np + 1], a0, a1, a2, a3, b2, b3);
        }
    }

    // ---- softmax ----
    const float scale = 0.17677669529663687f;  // 1/sqrt(32)
#pragma unroll
    for (int nt = 0; nt < 8; nt++)
#pragma unroll
        for (int i = 0; i < 4; i++) s[nt][i] *= scale;

    float m1 = -1e30f, m2 = -1e30f;
#pragma unroll
    for (int nt = 0; nt < 8; nt++) {
        m1 = fmaxf(m1, fmaxf(s[nt][0], s[nt][1]));
        m2 = fmaxf(m2, fmaxf(s[nt][2], s[nt][3]));
    }
    m1 = fmaxf(m1, __shfl_xor_sync(0xffffffffu, m1, 1));
    m1 = fmaxf(m1, __shfl_xor_sync(0xffffffffu, m1, 2));
    m2 = fmaxf(m2, __shfl_xor_sync(0xffffffffu, m2, 1));
    m2 = fmaxf(m2, __shfl_xor_sync(0xffffffffu, m2, 2));

    float sum1 = 0.0f, sum2 = 0.0f;
#pragma unroll
    for (int nt = 0; nt < 8; nt++) {
        s[nt][0] = __expf(s[nt][0] - m1);
        s[nt][1] = __expf(s[nt][1] - m1);
        s[nt][2] = __expf(s[nt][2] - m2);
        s[nt][3] = __expf(s[nt][3] - m2);
        sum1 += s[nt][0] + s[nt][1];
        sum2 += s[nt][2] + s[nt][3];
    }
    sum1 += __shfl_xor_sync(0xffffffffu, sum1, 1);
    sum1 += __shfl_xor_sync(0xffffffffu, sum1, 2);
    sum2 += __shfl_xor_sync(0xffffffffu, sum2, 1);
    sum2 += __shfl_xor_sync(0xffffffffu, sum2, 2);
    const float inv1 = 1.0f / sum1;
    const float inv2 = 1.0f / sum2;

    // ---- O = P V: P straight from registers; V B-frags via ldmatrix.trans.
    const uint32_t bV = smem_u32(&Vs[0][0]) + (t01 * 8 + l7) * 80 + t23 * 16;
    float o[4][4];
#pragma unroll
    for (int nt = 0; nt < 4; nt++)
#pragma unroll
        for (int i = 0; i < 4; i++) o[nt][i] = 0.0f;

#pragma unroll
    for (int g = 0; g < 4; g++) {
        const uint32_t a0 = packh2(s[2 * g][0] * inv1, s[2 * g][1] * inv1);
        const uint32_t a1 = packh2(s[2 * g][2] * inv2, s[2 * g][3] * inv2);
        const uint32_t a2 = packh2(s[2 * g + 1][0] * inv1, s[2 * g + 1][1] * inv1);
        const uint32_t a3 = packh2(s[2 * g + 1][2] * inv2, s[2 * g + 1][3] * inv2);
#pragma unroll
        for (int vp = 0; vp < 2; vp++) {
            uint32_t b0, b1, b2, b3;
            LDSM4T(b0, b1, b2, b3, bV + g * (16 * 80) + vp * 32);
            MMA_F16(o[2 * vp],     a0, a1, a2, a3, b0, b1);
            MMA_F16(o[2 * vp + 1], a0, a1, a2, a3, b2, b3);
        }
    }

    // Epilogue: head-major, pair-permuted within the 32-dk block
    // (Wo-GEMM A-input layout). Coalesced 64B-stride rows.
    const int srow = w * 16 + r8;
#pragma unroll
    for (int nt = 0; nt < 4; nt++) {
        const int off = (nt >> 1) * 16 + 4 * c + 2 * (nt & 1);
        *(__half2*)&At[base + srow * 32 + off] =
            __floats2half2_rn(o[nt][0], o[nt][1]);
        *(__half2*)&At[base + (srow + 8) * 32 + off] =
            __floats2half2_rn(o[nt][2], o[nt][3]);
    }
}

// ======================== launch ===========================================
extern "C" void kernel_launch(void* const* d_in, const int* in_sizes, int n_in,
                              void* d_out, int out_size) {
    (void)in_sizes; (void)n_in; (void)out_size;
    const float* x  = (const float*)d_in[0];
    const float* Wq = (const float*)d_in[1];
    const float* Wk = (const float*)d_in[2];
    const float* Wv = (const float*)d_in[3];
    const float* Wo = (const float*)d_in[4];
    float* out = (float*)d_out;

    void *pxh, *pwh, *pqkv, *pat;
    cudaGetSymbolAddress(&pxh, g_xh);
    cudaGetSymbolAddress(&pwh, g_wh);
    cudaGetSymbolAddress(&pqkv, g_qkvh);
    cudaGetSymbolAddress(&pat, g_ath);

    cudaFuncSetAttribute(gemm_qkv,
                         cudaFuncAttributeMaxDynamicSharedMemorySize, GSMEM);
    cudaFuncSetAttribute(gemm_wo,
                         cudaFuncAttributeMaxDynamicSharedMemorySize, GSMEM);

    prep_all<<<PREPX_BLOCKS + 256, 256>>>(x, Wq, Wk, Wv, Wo,
                                          (__half*)pxh, (__half*)pwh);

    // Fused Q,K,V projections -> head-major fp16.
    gemm_qkv<<<dim3(12, M_ROWS / 128), 128, GSMEM>>>(
        (const __half*)pxh, (const __half*)pwh, (__half*)pqkv, MS);

    const __half* q = (const __half*)pqkv;
    const __half* k = q + MS;
    const __half* v = k + MS;
    attn64_f16<<<M_ROWS / SEQ * NUM_HEADS, 128>>>(q, k, v, (__half*)pat);

    // Output projection: gather head-major A, plain fp32 output.
    gemm_wo<<<dim3(4, M_ROWS / 128), 128, GSMEM>>>(
        (const __half*)pat, (const __half*)pwh + 3 * WELEMS, out);
}

// round 15
// speedup vs baseline: 1.0631x; 1.0631x over previous
#include <cuda_runtime.h>
#include <cuda_fp16.h>
#include <cstdint>

// ---------------------------------------------------------------------------
// x:(2048,64,512) fp32, Wq/Wk/Wv/Wo:(512,512) fp32
// out = SDPA(x@WqT, x@WkT, x@WvT) @ WoT    H=16, dk=32, S=64
//
// R15 = R13 GEMM config (3-stage cp.async, launch_bounds(128,2), split
// qkv/wo kernels — measured best) + R14's merged single-launch prep.
// R14 disproved the occupancy theory (3 CTAs/SM: tensor% flat, slower);
// legacy HMMA dispatch (~12cyc/SMSP, half-rate active) is the GEMM floor.
// Attention unchanged (at its DRAM/issue floor). Numerics bit-identical.
// ---------------------------------------------------------------------------

#define D_MODEL   512
#define M_ROWS    131072
#define NUM_HEADS 16
#define SEQ       64
#define DK        32

#define MS        ((size_t)M_ROWS * D_MODEL)
#define WELEMS    ((size_t)D_MODEL * D_MODEL)

__device__ __half g_xh[MS];            // x, fp16, pair-permuted along k
__device__ __half g_wh[4 * WELEMS];    // Wq,Wk,Wv,Wo fp16, pair-permuted
__device__ __half g_qkvh[3 * MS];      // q, k, v : head-major [b,h,s,dk]
__device__ __half g_ath[MS];           // attn out: head-major, pair-permuted

// ======================== helpers ==========================================
__device__ __forceinline__ uint32_t smem_u32(const void* p) {
    uint32_t a;
    asm("{ .reg .u64 t; cvta.to.shared.u64 t, %1; cvt.u32.u64 %0, t; }"
        : "=r"(a) : "l"(p));
    return a;
}

#define MMA_F16(d, a0, a1, a2, a3, b0, b1)                                     \
    asm volatile(                                                              \
        "mma.sync.aligned.m16n8k16.row.col.f32.f16.f16.f32 "                   \
        "{%0,%1,%2,%3}, {%4,%5,%6,%7}, {%8,%9}, {%0,%1,%2,%3};"                \
        : "+f"(d[0]), "+f"(d[1]), "+f"(d[2]), "+f"(d[3])                       \
        : "r"(a0), "r"(a1), "r"(a2), "r"(a3), "r"(b0), "r"(b1))

#define LDSM4(r0, r1, r2, r3, a)                                               \
    asm volatile("ldmatrix.sync.aligned.m8n8.x4.shared.b16 "                   \
                 "{%0,%1,%2,%3}, [%4];"                                        \
                 : "=r"(r0), "=r"(r1), "=r"(r2), "=r"(r3) : "r"(a))
#define LDSM4T(r0, r1, r2, r3, a)                                              \
    asm volatile("ldmatrix.sync.aligned.m8n8.x4.trans.shared.b16 "             \
                 "{%0,%1,%2,%3}, [%4];"                                        \
                 : "=r"(r0), "=r"(r1), "=r"(r2), "=r"(r3) : "r"(a))

#define CPA16(sa, gp)                                                          \
    asm volatile("cp.async.cg.shared.global [%0], [%1], 16;"                   \
                 :: "r"(sa), "l"(gp) : "memory")
#define CPA_COMMIT() asm volatile("cp.async.commit_group;" ::: "memory")
#define CPA_WAIT1()  asm volatile("cp.async.wait_group 1;" ::: "memory")
#define CPA_WAIT0()  asm volatile("cp.async.wait_group 0;" ::: "memory")
#define LDS64(v, a)                                                            \
    asm volatile("ld.shared.v2.u32 {%0,%1}, [%2];"                             \
                 : "=r"((v).x), "=r"((v).y) : "r"(a))

__device__ __forceinline__ uint32_t packh2(float a, float b) {
    __half2 h = __floats2half2_rn(a, b);
    return *(uint32_t*)&h;
}

// Head-major address for logical (row=(b,s), col=(h,dk)) in halves.
__device__ __forceinline__ size_t hm_idx(int row, int col) {
    return ((size_t)(row >> 6) << 15) + ((size_t)(col >> 5) << 11) +
           ((size_t)(row & 63) << 5) + (size_t)(col & 31);
}

// ======================== prep (x + all W in one launch) ===================
__device__ __forceinline__ void prep16(const float* f, uint32_t* o) {
#pragma unroll
    for (int j = 0; j < 8; j++)
        o[((j & 3) << 1) + (j >> 2)] = packh2(f[2 * j], f[2 * j + 1]);
}

#define PREPX_BLOCKS 16384

__global__ void __launch_bounds__(256)
prep_all(const float* __restrict__ x,
         const float* __restrict__ w0, const float* __restrict__ w1,
         const float* __restrict__ w2, const float* __restrict__ w3,
         __half* __restrict__ xh, __half* __restrict__ wh) {
    const int bid = blockIdx.x;
    const float* src;
    __half* dst;
    size_t g;
    if (bid < PREPX_BLOCKS) {
        g   = (size_t)bid * 256 + threadIdx.x;   // group of 16 in x
        src = x + g * 16;
        dst = xh;
    } else {
        size_t gw = (size_t)(bid - PREPX_BLOCKS) * 256 + threadIdx.x;
        int wsel = (int)(gw >> 14);               // 16384 groups per W
        const float* w = wsel == 0 ? w0 : wsel == 1 ? w1 : wsel == 2 ? w2 : w3;
        src = w + (gw & 16383) * 16;
        dst = wh;
        g   = gw;
    }
    float f[16];
#pragma unroll
    for (int q = 0; q < 4; q++)
        *(float4*)&f[4 * q] = ((const float4*)src)[q];
    uint32_t o[8];
    prep16(f, o);
    ((uint4*)dst)[2 * g]     = make_uint4(o[0], o[1], o[2], o[3]);
    ((uint4*)dst)[2 * g + 1] = make_uint4(o[4], o[5], o[6], o[7]);
}

// ======================== GEMM common pieces ===============================
// Block 128x128, BK=64 halves (128B/row), 128 threads = 4 warps (2Mx2N),
// warp tile 64x64. Stage = A(16KB)+B(16KB); 3 stages = 96KB; 2 CTAs/SM.
#define GSTAGE  32768
#define GSMEM   (3 * GSTAGE + 128)

#define GEMM_COMPUTE(sbase, s)                                                 \
    do {                                                                       \
        const uint32_t sA =                                                    \
            (sbase) + (s)*GSTAGE + (wm * 64 + r8) * 128 + 8 * (c & 1);         \
        const uint32_t sB = (sbase) + (s)*GSTAGE + 16384 + wn * 8192 +         \
                            r8 * 128 + 8 * (c & 1);                            \
        _Pragma("unroll") for (int g = 0; g < 4; g++) {                        \
            const uint32_t csw = (uint32_t)(((2 * g + (c >> 1)) ^ r8) << 4);   \
            uint2 lo, hi;                                                      \
            unsigned a0[4], a1[4], a2[4], a3[4], b0[8], b1[8];                 \
            _Pragma("unroll") for (int mt = 0; mt < 4; mt++) {                 \
                LDS64(lo, sA + mt * 2048 + csw);                               \
                LDS64(hi, sA + mt * 2048 + 1024 + csw);                        \
                a0[mt] = lo.x; a2[mt] = lo.y; a1[mt] = hi.x; a3[mt] = hi.y;    \
            }                                                                  \
            _Pragma("unroll") for (int nt = 0; nt < 8; nt++) {                 \
                LDS64(lo, sB + nt * 1024 + csw);                               \
                b0[nt] = lo.x; b1[nt] = lo.y;                                  \
            }                                                                  \
            _Pragma("unroll") for (int mt = 0; mt < 4; mt++)                   \
                _Pragma("unroll") for (int nt = 0; nt < 8; nt++)               \
                    MMA_F16(acc[mt][nt], a0[mt], a1[mt], a2[mt], a3[mt],       \
                            b0[nt], b1[nt]);                                   \
        }                                                                      \
    } while (0)

// ======================== GEMM: QKV (fp16 A -> head-major fp16 C) ==========
__global__ void __launch_bounds__(128, 2)
gemm_qkv(const __half* __restrict__ A, const __half* __restrict__ Wt,
         __half* __restrict__ C, size_t c_stride) {
    extern __shared__ char dsmem[];
    const uint32_t sb = (smem_u32(dsmem) + 127u) & ~127u;

    const int tid  = threadIdx.x;
    const int lane = tid & 31;
    const int wid  = tid >> 5;
    const int wm   = wid & 1;
    const int wn   = wid >> 1;
    const int c    = lane & 3;
    const int r8   = lane >> 2;

    const int nb   = blockIdx.x;
    const int wsel = nb >> 2;
    const int n0   = (nb & 3) * 128;
    const int m0   = blockIdx.y * 128;

    const __half* Aw = A + (size_t)m0 * 512;
    const __half* Bw = Wt + (size_t)wsel * WELEMS + (size_t)n0 * 512;

    float acc[4][8][4];
#pragma unroll
    for (int mt = 0; mt < 4; mt++)
#pragma unroll
        for (int nt = 0; nt < 8; nt++)
#pragma unroll
            for (int i = 0; i < 4; i++) acc[mt][nt][i] = 0.0f;

    auto load_stage = [&](int s, int kt) {
        const uint32_t stage = sb + s * GSTAGE;
#pragma unroll
        for (int i = 0; i < 16; i++) {
            const int cid = tid + i * 128;
            const int isB = cid >> 10;
            const int r   = (cid >> 3) & 127;
            const int ch  = cid & 7;
            const uint32_t so =
                stage + isB * 16384 + r * 128 + (((ch ^ (r & 7)) << 4));
            const __half* gp =
                (isB ? Bw : Aw) + (size_t)r * 512 + kt * 64 + ch * 8;
            CPA16(so, gp);
        }
        CPA_COMMIT();
    };

    load_stage(0, 0);
    load_stage(1, 1);

    int scur = 0, snext = 1, sload = 2;
#pragma unroll 1
    for (int kt = 0; kt < 8; kt++) {
        if (kt < 7) { CPA_WAIT1(); } else { CPA_WAIT0(); }
        __syncthreads();
        if (kt + 2 < 8) load_stage(sload, kt + 2);
        GEMM_COMPUTE(sb, scur);
        const int t = scur; scur = snext; snext = sload; sload = t;
    }

    __half* Ch = C + (size_t)wsel * c_stride;
#pragma unroll
    for (int mt = 0; mt < 4; mt++) {
        const int row = m0 + wm * 64 + mt * 16 + r8;
#pragma unroll
        for (int nt = 0; nt < 8; nt++) {
            const int off = n0 + wn * 64 + nt * 8 + 2 * c;
            const size_t a = hm_idx(row, off);
            *(__half2*)&Ch[a] =
                __floats2half2_rn(acc[mt][nt][0], acc[mt][nt][1]);
            *(__half2*)&Ch[a + 256] =   // s+8 -> +8*32 halves
                __floats2half2_rn(acc[mt][nt][2], acc[mt][nt][3]);
        }
    }
}

// ======================== GEMM: Wo (head-major gather A -> fp32 C) =========
__global__ void __launch_bounds__(128, 2)
gemm_wo(const __half* __restrict__ A, const __half* __restrict__ Wt,
        float* __restrict__ C) {
    extern __shared__ char dsmem[];
    const uint32_t sb = (smem_u32(dsmem) + 127u) & ~127u;

    const int tid  = threadIdx.x;
    const int lane = tid & 31;
    const int wid  = tid >> 5;
    const int wm   = wid & 1;
    const int wn   = wid >> 1;
    const int c    = lane & 3;
    const int r8   = lane >> 2;

    const int n0 = blockIdx.x * 128;
    const int m0 = blockIdx.y * 128;

    const __half* Bw = Wt + (size_t)n0 * 512;

    float acc[4][8][4];
#pragma unroll
    for (int mt = 0; mt < 4; mt++)
#pragma unroll
        for (int nt = 0; nt < 8; nt++)
#pragma unroll
            for (int i = 0; i < 4; i++) acc[mt][nt][i] = 0.0f;

    auto load_stage = [&](int s, int kt) {
        const uint32_t stage = sb + s * GSTAGE;
#pragma unroll
        for (int i = 0; i < 16; i++) {
            const int cid = tid + i * 128;
            const int isB = cid >> 10;
            const int r   = (cid >> 3) & 127;
            const int ch  = cid & 7;
            const uint32_t so =
                stage + isB * 16384 + r * 128 + (((ch ^ (r & 7)) << 4));
            const __half* gp =
                isB ? (Bw + (size_t)r * 512 + kt * 64 + ch * 8)
                    : (A + hm_idx(m0 + r, kt * 64 + ch * 8));
            CPA16(so, gp);
        }
        CPA_COMMIT();
    };

    load_stage(0, 0);
    load_stage(1, 1);

    int scur = 0, snext = 1, sload = 2;
#pragma unroll 1
    for (int kt = 0; kt < 8; kt++) {
        if (kt < 7) { CPA_WAIT1(); } else { CPA_WAIT0(); }
        __syncthreads();
        if (kt + 2 < 8) load_stage(sload, kt + 2);
        GEMM_COMPUTE(sb, scur);
        const int t = scur; scur = snext; snext = sload; sload = t;
    }

#pragma unroll
    for (int mt = 0; mt < 4; mt++) {
        const int row = m0 + wm * 64 + mt * 16 + r8;
#pragma unroll
        for (int nt = 0; nt < 8; nt++) {
            const int col = n0 + wn * 64 + nt * 8 + 2 * c;
            *(float2*)&C[(size_t)row * 512 + col] =
                make_float2(acc[mt][nt][0], acc[mt][nt][1]);
            *(float2*)&C[(size_t)(row + 8) * 512 + col] =
                make_float2(acc[mt][nt][2], acc[mt][nt][3]);
        }
    }
}

// ======================== attention (fp16 mma.sync + ldmatrix) =============
// One block (128 threads) per (batch, head). q,k,v head-major: each tensor
// slab for this block is 4KB CONTIGUOUS -> fully coalesced staging.
// Row stride 40 halves (80B) keeps every ldmatrix phase conflict-free.
// P stays in registers (S-fragment == PV A-fragment).
__global__ void __launch_bounds__(128, 8)
attn64_f16(const __half* __restrict__ Q, const __half* __restrict__ K,
           const __half* __restrict__ V, __half* __restrict__ At) {
    __shared__ __half Qs[64][40];
    __shared__ __half Ks[64][40];
    __shared__ __half Vs[64][40];

    const int tid  = threadIdx.x;
    const int lane = tid & 31;
    const int w    = tid >> 5;
    const int c    = lane & 3;
    const int r8   = lane >> 2;

    const int bh = blockIdx.x;                 // b*16 + h
    const size_t base = (size_t)bh * 2048;     // [b,h] slab, 64x32 halves

    {
        const uint4* qg = (const uint4*)(Q + base);
        const uint4* kg = (const uint4*)(K + base);
        const uint4* vg = (const uint4*)(V + base);
#pragma unroll
        for (int i = 0; i < 2; i++) {
            const int ci  = tid + i * 128;
            const int row = ci >> 2, p = ci & 3;
            *(uint4*)&Qs[row][p * 8] = qg[ci];
            *(uint4*)&Ks[row][p * 8] = kg[ci];
            *(uint4*)&Vs[row][p * 8] = vg[ci];
        }
    }
    __syncthreads();

    const int l7  = lane & 7;
    const int t01 = (lane >> 3) & 1;
    const int t23 = lane >> 4;

    // ---- S = Q K^T  (M=16/warp, N=64, K=32 -> 2 k16 groups) ----
    const uint32_t aQ = smem_u32(&Qs[0][0]) +
                        (w * 16 + t01 * 8 + l7) * 80 + t23 * 16;
    const uint32_t bK = smem_u32(&Ks[0][0]) +
                        (t23 * 8 + l7) * 80 + t01 * 16;
    float s[8][4];
#pragma unroll
    for (int nt = 0; nt < 8; nt++)
#pragma unroll
        for (int i = 0; i < 4; i++) s[nt][i] = 0.0f;

#pragma unroll
    for (int g = 0; g < 2; g++) {
        uint32_t a0, a1, a2, a3;
        LDSM4(a0, a1, a2, a3, aQ + g * 32);
#pragma unroll
        for (int np = 0; np < 4; np++) {
            uint32_t b0, b1, b2, b3;
            LDSM4(b0, b1, b2, b3, bK + np * (16 * 80) + g * 32);
            MMA_F16(s[2 * np],     a0, a1, a2, a3, b0, b1);
            MMA_F16(s[2 * np + 1], a0, a1, a2, a3, b2, b3);
        }
    }

    // ---- softmax ----
    const float scale = 0.17677669529663687f;  // 1/sqrt(32)
#pragma unroll
    for (int nt = 0; nt < 8; nt++)
#pragma unroll
        for (int i = 0; i < 4; i++) s[nt][i] *= scale;

    float m1 = -1e30f, m2 = -1e30f;
#pragma unroll
    for (int nt = 0; nt < 8; nt++) {
        m1 = fmaxf(m1, fmaxf(s[nt][0], s[nt][1]));
        m2 = fmaxf(m2, fmaxf(s[nt][2], s[nt][3]));
    }
    m1 = fmaxf(m1, __shfl_xor_sync(0xffffffffu, m1, 1));
    m1 = fmaxf(m1, __shfl_xor_sync(0xffffffffu, m1, 2));
    m2 = fmaxf(m2, __shfl_xor_sync(0xffffffffu, m2, 1));
    m2 = fmaxf(m2, __shfl_xor_sync(0xffffffffu, m2, 2));

    float sum1 = 0.0f, sum2 = 0.0f;
#pragma unroll
    for (int nt = 0; nt < 8; nt++) {
        s[nt][0] = __expf(s[nt][0] - m1);
        s[nt][1] = __expf(s[nt][1] - m1);
        s[nt][2] = __expf(s[nt][2] - m2);
        s[nt][3] = __expf(s[nt][3] - m2);
        sum1 += s[nt][0] + s[nt][1];
        sum2 += s[nt][2] + s[nt][3];
    }
    sum1 += __shfl_xor_sync(0xffffffffu, sum1, 1);
    sum1 += __shfl_xor_sync(0xffffffffu, sum1, 2);
    sum2 += __shfl_xor_sync(0xffffffffu, sum2, 1);
    sum2 += __shfl_xor_sync(0xffffffffu, sum2, 2);
    const float inv1 = 1.0f / sum1;
    const float inv2 = 1.0f / sum2;

    // ---- O = P V: P straight from registers; V B-frags via ldmatrix.trans.
    const uint32_t bV = smem_u32(&Vs[0][0]) + (t01 * 8 + l7) * 80 + t23 * 16;
    float o[4][4];
#pragma unroll
    for (int nt = 0; nt < 4; nt++)
#pragma unroll
        for (int i = 0; i < 4; i++) o[nt][i] = 0.0f;

#pragma unroll
    for (int g = 0; g < 4; g++) {
        const uint32_t a0 = packh2(s[2 * g][0] * inv1, s[2 * g][1] * inv1);
        const uint32_t a1 = packh2(s[2 * g][2] * inv2, s[2 * g][3] * inv2);
        const uint32_t a2 = packh2(s[2 * g + 1][0] * inv1, s[2 * g + 1][1] * inv1);
        const uint32_t a3 = packh2(s[2 * g + 1][2] * inv2, s[2 * g + 1][3] * inv2);
#pragma unroll
        for (int vp = 0; vp < 2; vp++) {
            uint32_t b0, b1, b2, b3;
            LDSM4T(b0, b1, b2, b3, bV + g * (16 * 80) + vp * 32);
            MMA_F16(o[2 * vp],     a0, a1, a2, a3, b0, b1);
            MMA_F16(o[2 * vp + 1], a0, a1, a2, a3, b2, b3);
        }
    }

    // Epilogue: head-major, pair-permuted within the 32-dk block
    // (Wo-GEMM A-input layout). Coalesced 64B-stride rows.
    const int srow = w * 16 + r8;
#pragma unroll
    for (int nt = 0; nt < 4; nt++) {
        const int off = (nt >> 1) * 16 + 4 * c + 2 * (nt & 1);
        *(__half2*)&At[base + srow * 32 + off] =
            __floats2half2_rn(o[nt][0], o[nt][1]);
        *(__half2*)&At[base + (srow + 8) * 32 + off] =
            __floats2half2_rn(o[nt][2], o[nt][3]);
    }
}

// ======================== launch ===========================================
extern "C" void kernel_launch(void* const* d_in, const int* in_sizes, int n_in,
                              void* d_out, int out_size) {
    (void)in_sizes; (void)n_in; (void)out_size;
    const float* x  = (const float*)d_in[0];
    const float* Wq = (const float*)d_in[1];
    const float* Wk = (const float*)d_in[2];
    const float* Wv = (const float*)d_in[3];
    const float* Wo = (const float*)d_in[4];
    float* out = (float*)d_out;

    void *pxh, *pwh, *pqkv, *pat;
    cudaGetSymbolAddress(&pxh, g_xh);
    cudaGetSymbolAddress(&pwh, g_wh);
    cudaGetSymbolAddress(&pqkv, g_qkvh);
    cudaGetSymbolAddress(&pat, g_ath);

    cudaFuncSetAttribute(gemm_qkv,
                         cudaFuncAttributeMaxDynamicSharedMemorySize, GSMEM);
    cudaFuncSetAttribute(gemm_wo,
                         cudaFuncAttributeMaxDynamicSharedMemorySize, GSMEM);

    prep_all<<<PREPX_BLOCKS + 256, 256>>>(x, Wq, Wk, Wv, Wo,
                                          (__half*)pxh, (__half*)pwh);

    // Fused Q,K,V projections -> head-major fp16.
    gemm_qkv<<<dim3(12, M_ROWS / 128), 128, GSMEM>>>(
        (const __half*)pxh, (const __half*)pwh, (__half*)pqkv, MS);

    const __half* q = (const __half*)pqkv;
    const __half* k = q + MS;
    const __half* v = k + MS;
    attn64_f16<<<M_ROWS / SEQ * NUM_HEADS, 128>>>(q, k, v, (__half*)pat);

    // Output projection: gather head-major A, plain fp32 output.
    gemm_wo<<<dim3(4, M_ROWS / 128), 128, GSMEM>>>(
        (const __half*)pat, (const __half*)pwh + 3 * WELEMS, out);
}